// round 14
// baseline (speedup 1.0000x reference)
#include <cuda_runtime.h>
#include <cstdint>

#define TT    101
#define W0F   44.0f
#define NTHR  384
#define WPC   (NTHR / 32)   // warps per CTA
#define PPW   16            // points per warp (m16 tile)

// ---- dynamic smem layout (bytes) ----
#define BF_OFF    0                   // W2 f16 frags [ntp][kt][g][tig] uint4: 32 KB
#define P1_OFF    32768               // float4[128]: (44*W1x, 44*W1y, 44*b1, 0)
#define WB_OFF    (P1_OFF + 2048)     // float4[128]: (W3x, W3y, 44*b2, 0)
#define DTS_OFF   (WB_OFF + 2048)     // float[100]
#define B3_OFF    (DTS_OFF + 512)     // float[2]
#define SMEM_TOTAL (B3_OFF + 16)

// pack two f32 -> f16x2, first arg in the LOW half
static __device__ __forceinline__ uint32_t h2(float lo, float hi) {
    uint32_t r;
    asm("cvt.rn.f16x2.f32 %0, %1, %2;" : "=r"(r) : "f"(hi), "f"(lo));
    return r;
}

static __device__ __forceinline__ void mma16(float* d, uint32_t a0, uint32_t a1,
                                             uint32_t a2, uint32_t a3,
                                             uint32_t b0, uint32_t b1) {
    asm volatile(
        "mma.sync.aligned.m16n8k16.row.col.f32.f16.f16.f32 "
        "{%0,%1,%2,%3}, {%4,%5,%6,%7}, {%8,%9}, {%0,%1,%2,%3};"
        : "+f"(d[0]), "+f"(d[1]), "+f"(d[2]), "+f"(d[3])
        : "r"(a0), "r"(a1), "r"(a2), "r"(a3), "r"(b0), "r"(b1));
}

// One SIREN vector-field eval for this warp's 16 points (lane l < 16 owns
// point l = its m16 row). Per kt: 8 layer-1 sins -> A frags (4 regs), then
// 16 MMAs into 16 independent acc quads (depth-8 chains). Epilogue: 64 sins
// + W3 fold + quad reduce + shfl route back to owner lanes.
__device__ __noinline__ void feval(float px, float py, const char* sm,
                                   int lane, float b3x, float b3y,
                                   float& fx, float& fy) {
    const int g = lane >> 2, tig = lane & 3;

    // coords of the 2 rows (g, g+8) whose fragment slots this lane owns
    const float rx0 = __shfl_sync(0xffffffffu, px, g);
    const float ry0 = __shfl_sync(0xffffffffu, py, g);
    const float rx1 = __shfl_sync(0xffffffffu, px, g + 8);
    const float ry1 = __shfl_sync(0xffffffffu, py, g + 8);

    const float4* P1 = reinterpret_cast<const float4*>(sm + P1_OFF);
    const float4* WB = reinterpret_cast<const float4*>(sm + WB_OFF);
    const uint4* BF = reinterpret_cast<const uint4*>(sm + BF_OFF);

    float acc[64];  // [nt(16)][4]: 16 independent depth-8 MMA chains
#pragma unroll
    for (int i = 0; i < 64; i++) acc[i] = 0.0f;

#pragma unroll
    for (int kt = 0; kt < 8; kt++) {
        const int c0 = 16 * kt + 2 * tig;
        float4 pA = P1[c0], pB = P1[c0 + 1], pC = P1[c0 + 8], pD = P1[c0 + 9];

        // A fragment for rows {g, g+8}, k-cols {c0, c0+1} and {c0+8, c0+9}
        float sA0 = __sinf(fmaf(rx0, pA.x, fmaf(ry0, pA.y, pA.z)));
        float sB0 = __sinf(fmaf(rx0, pB.x, fmaf(ry0, pB.y, pB.z)));
        float sC0 = __sinf(fmaf(rx0, pC.x, fmaf(ry0, pC.y, pC.z)));
        float sD0 = __sinf(fmaf(rx0, pD.x, fmaf(ry0, pD.y, pD.z)));
        float sA1 = __sinf(fmaf(rx1, pA.x, fmaf(ry1, pA.y, pA.z)));
        float sB1 = __sinf(fmaf(rx1, pB.x, fmaf(ry1, pB.y, pB.z)));
        float sC1 = __sinf(fmaf(rx1, pC.x, fmaf(ry1, pC.y, pC.z)));
        float sD1 = __sinf(fmaf(rx1, pD.x, fmaf(ry1, pD.y, pD.z)));
        uint32_t a0 = h2(sA0, sB0);   // row g,   low-k pair
        uint32_t a1 = h2(sA1, sB1);   // row g+8, low-k pair
        uint32_t a2 = h2(sC0, sD0);   // row g,   high-k pair
        uint32_t a3 = h2(sC1, sD1);   // row g+8, high-k pair

#pragma unroll
        for (int ntp = 0; ntp < 8; ntp++) {
            uint4 b = BF[(ntp * 8 + kt) * 32 + g * 4 + tig];
            mma16(acc + (2 * ntp) * 4,     a0, a1, a2, a3, b.x, b.y);
            mma16(acc + (2 * ntp + 1) * 4, a0, a1, a2, a3, b.z, b.w);
        }
    }

    // ---- layer 3: f = sin(44*D + 44*b2) @ W3 + b3 ----
    float ps[4];  // (fx,fy) partials for rows g and g+8
#pragma unroll
    for (int i = 0; i < 4; i++) ps[i] = 0.0f;
#pragma unroll
    for (int nt = 0; nt < 16; nt++) {
        float4 w0 = WB[8 * nt + 2 * tig];
        float4 w1 = WB[8 * nt + 2 * tig + 1];
        const float* d = acc + nt * 4;
        float h00 = __sinf(fmaf(W0F, d[0], w0.z));  // row g,   col 2tig
        float h01 = __sinf(fmaf(W0F, d[1], w1.z));  // row g,   col 2tig+1
        float h10 = __sinf(fmaf(W0F, d[2], w0.z));  // row g+8
        float h11 = __sinf(fmaf(W0F, d[3], w1.z));
        ps[0] = fmaf(h00, w0.x, fmaf(h01, w1.x, ps[0]));
        ps[1] = fmaf(h00, w0.y, fmaf(h01, w1.y, ps[1]));
        ps[2] = fmaf(h10, w0.x, fmaf(h11, w1.x, ps[2]));
        ps[3] = fmaf(h10, w0.y, fmaf(h11, w1.y, ps[3]));
    }
    // reduce across the 4 lanes of each thread-group (lane bits 0,1)
#pragma unroll
    for (int d = 1; d <= 2; d <<= 1)
#pragma unroll
        for (int i = 0; i < 4; i++)
            ps[i] += __shfl_xor_sync(0xffffffffu, ps[i], d);

    // route: point p (= row p) owned by lane p; its sums sit on lane group
    // g = p&7 (src lane (p&7)*4), entries {0,1} for p<8 else {2,3}
    const int src = (lane & 7) * 4;
    float v0 = __shfl_sync(0xffffffffu, ps[0], src);
    float v1 = __shfl_sync(0xffffffffu, ps[1], src);
    float v2 = __shfl_sync(0xffffffffu, ps[2], src);
    float v3 = __shfl_sync(0xffffffffu, ps[3], src);
    const bool lo = (lane & 15) < 8;
    fx = b3x + (lo ? v0 : v2);
    fy = b3y + (lo ? v1 : v3);
}

extern "C" __global__ void __launch_bounds__(NTHR, 1)
node_hmma(const float* __restrict__ t, const float* __restrict__ x0,
          const float* __restrict__ W1, const float* __restrict__ b1,
          const float* __restrict__ W2, const float* __restrict__ b2,
          const float* __restrict__ W3, const float* __restrict__ b3g,
          float* __restrict__ out, int N) {
    extern __shared__ char sm[];
    const int tid = threadIdx.x;
    const int lane = tid & 31;
    const int warp = tid >> 5;

    // ---- stage W2 as f16 fragment uint4s: [ntp][kt][g][tig] ----
    // .x/.y = B-frag (b0,b1) for n0 = 16ntp+g; .z/.w = same for n1 = n0+8
    for (int idx = tid; idx < 2048; idx += NTHR) {
        int tg = idx & 3, g = (idx >> 2) & 7, kt = (idx >> 5) & 7, ntp = idx >> 8;
        int n0 = 16 * ntp + g, n1 = n0 + 8;
        int k0 = 16 * kt + 2 * tg;
        uint4 v;
        v.x = h2(W2[k0 * 128 + n0],       W2[(k0 + 1) * 128 + n0]);
        v.y = h2(W2[(k0 + 8) * 128 + n0], W2[(k0 + 9) * 128 + n0]);
        v.z = h2(W2[k0 * 128 + n1],       W2[(k0 + 1) * 128 + n1]);
        v.w = h2(W2[(k0 + 8) * 128 + n1], W2[(k0 + 9) * 128 + n1]);
        reinterpret_cast<uint4*>(sm + BF_OFF)[idx] = v;
    }
    for (int k = tid; k < 128; k += NTHR) {
        reinterpret_cast<float4*>(sm + P1_OFF)[k] =
            make_float4(W0F * W1[k], W0F * W1[128 + k], W0F * b1[k], 0.0f);
        reinterpret_cast<float4*>(sm + WB_OFF)[k] =
            make_float4(W3[2 * k], W3[2 * k + 1], W0F * b2[k], 0.0f);
    }
    for (int s = tid; s < TT - 1; s += NTHR)
        reinterpret_cast<float*>(sm + DTS_OFF)[s] = t[s + 1] - t[s];
    if (tid < 2) reinterpret_cast<float*>(sm + B3_OFF)[tid] = b3g[tid];
    __syncthreads();  // only CTA-wide sync; warps independent afterwards

    const float b3x = reinterpret_cast<const float*>(sm + B3_OFF)[0];
    const float b3y = reinterpret_cast<const float*>(sm + B3_OFF)[1];

    // warp-global point tile: 16 points, lane l < 16 owns point l
    const int gwarp = blockIdx.x * WPC + warp;
    const int gid = gwarp * PPW + lane;
    const bool live = (lane < PPW) && (gid < N);
    float2 y = live ? reinterpret_cast<const float2*>(x0)[gid]
                    : make_float2(0.0f, 0.0f);
    float2* outv = reinterpret_cast<float2*>(out);
    if (live) outv[gid] = y;  // t = 0 row

    const float third = 1.0f / 3.0f;
#pragma unroll 1
    for (int s = 0; s < TT - 1; s++) {
        float dt = reinterpret_cast<const float*>(sm + DTS_OFF)[s];
        float k1x, k1y, k2x, k2y, k3x, k3y, k4x, k4y;
        // torchdiffeq rk4_alt (3/8-rule)
        feval(y.x, y.y, sm, lane, b3x, b3y, k1x, k1y);
        feval(y.x + dt * k1x * third, y.y + dt * k1y * third,
              sm, lane, b3x, b3y, k2x, k2y);
        feval(y.x + dt * (k2x - k1x * third), y.y + dt * (k2y - k1y * third),
              sm, lane, b3x, b3y, k3x, k3y);
        feval(y.x + dt * (k1x - k2x + k3x), y.y + dt * (k1y - k2y + k3y),
              sm, lane, b3x, b3y, k4x, k4y);
        y.x = y.x + (k1x + 3.0f * (k2x + k3x) + k4x) * dt * 0.125f;
        y.y = y.y + (k1y + 3.0f * (k2y + k3y) + k4y) * dt * 0.125f;
        if (live) outv[(size_t)(s + 1) * N + gid] = y;
    }
}

extern "C" void kernel_launch(void* const* d_in, const int* in_sizes, int n_in,
                              void* d_out, int out_size) {
    const float* t  = (const float*)d_in[0];
    const float* x0 = (const float*)d_in[1];
    const float* W1 = (const float*)d_in[2];
    const float* b1 = (const float*)d_in[3];
    const float* W2 = (const float*)d_in[4];
    const float* b2 = (const float*)d_in[5];
    const float* W3 = (const float*)d_in[6];
    const float* b3 = (const float*)d_in[7];
    int N = in_sizes[1] / 2;

    cudaFuncSetAttribute(node_hmma,
                         cudaFuncAttributeMaxDynamicSharedMemorySize, SMEM_TOTAL);
    int pts_per_cta = WPC * PPW;
    int grid = (N + pts_per_cta - 1) / pts_per_cta;
    node_hmma<<<grid, NTHR, SMEM_TOTAL>>>(t, x0, W1, b1, W2, b2, W3, b3,
                                          (float*)d_out, N);
}